// round 10
// baseline (speedup 1.0000x reference)
#include <cuda_runtime.h>
#include <math_constants.h>

#define NN 50000
#define EE 1600000
#define EP (EE + NN)
#define GG 64
#define IND 128
#define HIDD 64
#define SCAN_BLK 1024
#define NBLK ((NN + SCAN_BLK - 1) / SCAN_BLK)

// packed f32x2 helpers (sm_100+ PTX)
#define PACK_F32X2(out, lo, hi) \
    asm("mov.b64 %0, {%1, %2};" : "=l"(out) : "r"(lo), "r"(hi))
#define FMA_F32X2(d, a, b, c) \
    asm("fma.rn.f32x2 %0, %1, %2, %3;" : "=l"(d) : "l"(a), "l"(b), "l"(c))

// ---------------- device scratch (no allocations allowed) ----------------
__device__ __align__(16) float g_xl[NN * HIDD];
__device__ __align__(16) float g_xr[NN * HIDD];
__device__ __align__(16) float g_h[NN * HIDD];
__device__ int g_deg[NN];          // in-degree incl. self loop
__device__ int g_off[NN + 1];      // CSR offsets (exclusive)
__device__ int g_rank[EE];         // per-edge rank among same-dst (from count)
__device__ __align__(8) int2 g_csr[EP];  // packed {src, attr_bits} per CSR slot
__device__ int g_bsum[NBLK + 1];   // scan block sums
__device__ float g_pool[GG * HIDD];
__device__ float g_pcnt[GG];

// ---------------- init ----------------
__global__ void init_kernel() {
    int i = blockIdx.x * blockDim.x + threadIdx.x;
    if (i < NN) g_deg[i] = 1;   // slot 0 = self loop
    if (i < GG * HIDD) g_pool[i] = 0.f;
    if (i < GG) g_pcnt[i] = 0.f;
}

// ---------------- CSR build ----------------
// count + record rank: atomic return value is this edge's slot within its dst segment
__global__ void count_kernel(const int* __restrict__ ei) {
    int e = blockIdx.x * blockDim.x + threadIdx.x;
    if (e >= EE) return;
    int r = atomicAdd(&g_deg[ei[EE + e]], 1);
    g_rank[e] = r;   // in [1, indeg]; slot 0 reserved for self loop
}

// per-block inclusive scan (Hillis-Steele) of degrees
__global__ void scan1_kernel() {
    __shared__ int s[SCAN_BLK];
    int t = threadIdx.x;
    int i = blockIdx.x * SCAN_BLK + t;
    int v = (i < NN) ? g_deg[i] : 0;
    s[t] = v;
    __syncthreads();
#pragma unroll
    for (int o = 1; o < SCAN_BLK; o <<= 1) {
        int x = (t >= o) ? s[t - o] : 0;
        __syncthreads();
        s[t] += x;
        __syncthreads();
    }
    if (i < NN) g_off[i] = s[t];
    if (t == SCAN_BLK - 1) g_bsum[blockIdx.x] = s[t];
}

// exclusive scan of NBLK block sums
__global__ void scan2_kernel() {
    __shared__ int s[64];
    int t = threadIdx.x;
    int v = (t < NBLK) ? g_bsum[t] : 0;
    s[t] = v;
    __syncthreads();
#pragma unroll
    for (int o = 1; o < 64; o <<= 1) {
        int x = (t >= o) ? s[t - o] : 0;
        __syncthreads();
        s[t] += x;
        __syncthreads();
    }
    if (t < NBLK) g_bsum[t] = s[t] - v;  // exclusive
}

__global__ void scan3_kernel() {
    int i = blockIdx.x * SCAN_BLK + threadIdx.x;
    if (i < NN) g_off[i] = g_off[i] - g_deg[i] + g_bsum[blockIdx.x];
    if (i == 0) g_off[NN] = EP;
}

// atomic-free scatter: slot fully determined by off + rank; packed 8B store
__global__ void scatter_kernel(const int* __restrict__ ei, const float* __restrict__ ea) {
    int e = blockIdx.x * blockDim.x + threadIdx.x;
    if (e >= EE) return;
    int d = ei[EE + e];
    int pos = g_off[d] + g_rank[e];
    g_csr[pos] = make_int2(ei[e], __float_as_int(ea[e]));
}

// ---------------- node linear transforms: xl = h@Wl+bl, xr = h@Wr+br ----------------
// blockDim (16,16): thread = (channel quad c4, node). Packed f32x2 FMAs; W via LDG.128.
template <int K, bool FROM_H>
__global__ void linear_kernel(const float* __restrict__ x,
                              const float* __restrict__ Wl, const float* __restrict__ bl,
                              const float* __restrict__ Wr, const float* __restrict__ br) {
    __shared__ float sx[16 * K];
    int flat = threadIdx.y * 16 + threadIdx.x;
    int node0 = blockIdx.x * 16;   // NN divisible by 16
    const float* srcbase = FROM_H ? (const float*)g_h : x;
    const float4* s4 = (const float4*)(srcbase + node0 * K);
    float4* d4 = (float4*)sx;
#pragma unroll
    for (int i = flat; i < 16 * K / 4; i += 256) d4[i] = s4[i];
    __syncthreads();

    int node = node0 + threadIdx.y;
    int c4 = threadIdx.x;   // channels 4*c4 .. 4*c4+3
    const ulonglong2* Wl2 = (const ulonglong2*)Wl;
    const ulonglong2* Wr2 = (const ulonglong2*)Wr;
    ulonglong2 al = ((const ulonglong2*)bl)[c4];
    ulonglong2 ar = ((const ulonglong2*)br)[c4];
    const float* row = sx + threadIdx.y * K;
#pragma unroll 4
    for (int k = 0; k < K; k++) {
        ulonglong2 wl = Wl2[k * 16 + c4];
        ulonglong2 wr = Wr2[k * 16 + c4];
        float xv = row[k];
        unsigned long long xv2;
        unsigned xb = __float_as_uint(xv);
        PACK_F32X2(xv2, xb, xb);
        FMA_F32X2(al.x, wl.x, xv2, al.x);
        FMA_F32X2(al.y, wl.y, xv2, al.y);
        FMA_F32X2(ar.x, wr.x, xv2, ar.x);
        FMA_F32X2(ar.y, wr.y, xv2, ar.y);
    }
    ((ulonglong2*)g_xl)[node * 16 + c4] = al;
    ((ulonglong2*)g_xr)[node * 16 + c4] = ar;
}

// ---------------- fused GAT aggregation ----------------
// Warp per node. 4 edge-groups of 8 lanes; each group covers ALL 64 channels
// (8 ch/lane via 2x float4). Logit reduce = 3 shuffle stages within the group;
// groups accumulate independently (plain softmax -> no cross-group sync in loop);
// one 2-stage combine at the end. FIRST layer fuses self-loop mean-attr compute
// and writes csr[beg] for layer 2; layer 2 pools.
template <bool FIRST>
__global__ void gat_node_kernel(const float* __restrict__ We, const float* __restrict__ att,
                                const float* __restrict__ bias, const int* __restrict__ batch) {
    int gtid = blockIdx.x * blockDim.x + threadIdx.x;
    int node = gtid >> 5, lane = gtid & 31;
    if (node >= NN) return;
    int grp = lane >> 3, gl = lane & 7;
    int beg = g_off[node], end = g_off[node + 1];
    int start = FIRST ? beg + 1 : beg;

    const float4* XL = (const float4*)g_xl;
    float4 xr0 = ((const float4*)g_xr)[node * 16 + 2 * gl];
    float4 xr1 = ((const float4*)g_xr)[node * 16 + 2 * gl + 1];
    float4 w0 = ((const float4*)We)[2 * gl];
    float4 w1 = ((const float4*)We)[2 * gl + 1];
    float4 at0 = ((const float4*)att)[2 * gl];
    float4 at1 = ((const float4*)att)[2 * gl + 1];

    float den = 0.f, asum = 0.f;
    float4 acc0 = make_float4(0.f, 0.f, 0.f, 0.f);
    float4 acc1 = make_float4(0.f, 0.f, 0.f, 0.f);

#pragma unroll 2
    for (int p0 = start; p0 < end; p0 += 4) {
        int p = p0 + grp;
        bool valid = (p < end);
        int pc = valid ? p : end - 1;        // clamp to a valid (scatter-written) slot
        int2 c2 = __ldg(&g_csr[pc]);
        int s = c2.x;
        float a = __int_as_float(c2.y);
        float4 xl0 = XL[s * 16 + 2 * gl];
        float4 xl1 = XL[s * 16 + 2 * gl + 1];
        float v, part;
        v = fmaf(a, w0.x, xl0.x + xr0.x); v = fmaxf(v, 0.2f * v); part = v * at0.x;
        v = fmaf(a, w0.y, xl0.y + xr0.y); v = fmaxf(v, 0.2f * v); part = fmaf(v, at0.y, part);
        v = fmaf(a, w0.z, xl0.z + xr0.z); v = fmaxf(v, 0.2f * v); part = fmaf(v, at0.z, part);
        v = fmaf(a, w0.w, xl0.w + xr0.w); v = fmaxf(v, 0.2f * v); part = fmaf(v, at0.w, part);
        v = fmaf(a, w1.x, xl1.x + xr1.x); v = fmaxf(v, 0.2f * v); part = fmaf(v, at1.x, part);
        v = fmaf(a, w1.y, xl1.y + xr1.y); v = fmaxf(v, 0.2f * v); part = fmaf(v, at1.y, part);
        v = fmaf(a, w1.z, xl1.z + xr1.z); v = fmaxf(v, 0.2f * v); part = fmaf(v, at1.z, part);
        v = fmaf(a, w1.w, xl1.w + xr1.w); v = fmaxf(v, 0.2f * v); part = fmaf(v, at1.w, part);
        part += __shfl_xor_sync(0xffffffffu, part, 1);
        part += __shfl_xor_sync(0xffffffffu, part, 2);
        part += __shfl_xor_sync(0xffffffffu, part, 4);
        if (!valid) part = -CUDART_INF_F;    // pe = 0
        float pe = __expf(part);
        if (FIRST && valid) asum += a;
        acc0.x = fmaf(pe, xl0.x, acc0.x);
        acc0.y = fmaf(pe, xl0.y, acc0.y);
        acc0.z = fmaf(pe, xl0.z, acc0.z);
        acc0.w = fmaf(pe, xl0.w, acc0.w);
        acc1.x = fmaf(pe, xl1.x, acc1.x);
        acc1.y = fmaf(pe, xl1.y, acc1.y);
        acc1.z = fmaf(pe, xl1.z, acc1.z);
        acc1.w = fmaf(pe, xl1.w, acc1.w);
        den += pe;
    }

    // combine the 4 groups (offsets 8, 16); replicas stay identical afterwards
#define CMB(x) x += __shfl_xor_sync(0xffffffffu, x, 8); x += __shfl_xor_sync(0xffffffffu, x, 16);
    CMB(acc0.x) CMB(acc0.y) CMB(acc0.z) CMB(acc0.w)
    CMB(acc1.x) CMB(acc1.y) CMB(acc1.z) CMB(acc1.w)
    CMB(den)
    if (FIRST) { CMB(asum) }
#undef CMB

    if (FIRST) {
        // self edge: attr = mean of real incoming attrs; xl = own row
        float cnt = (float)(end - beg - 1);
        float a = asum / fmaxf(cnt, 1.f);
        float4 sl0 = XL[node * 16 + 2 * gl];
        float4 sl1 = XL[node * 16 + 2 * gl + 1];
        float v, part;
        v = fmaf(a, w0.x, sl0.x + xr0.x); v = fmaxf(v, 0.2f * v); part = v * at0.x;
        v = fmaf(a, w0.y, sl0.y + xr0.y); v = fmaxf(v, 0.2f * v); part = fmaf(v, at0.y, part);
        v = fmaf(a, w0.z, sl0.z + xr0.z); v = fmaxf(v, 0.2f * v); part = fmaf(v, at0.z, part);
        v = fmaf(a, w0.w, sl0.w + xr0.w); v = fmaxf(v, 0.2f * v); part = fmaf(v, at0.w, part);
        v = fmaf(a, w1.x, sl1.x + xr1.x); v = fmaxf(v, 0.2f * v); part = fmaf(v, at1.x, part);
        v = fmaf(a, w1.y, sl1.y + xr1.y); v = fmaxf(v, 0.2f * v); part = fmaf(v, at1.y, part);
        v = fmaf(a, w1.z, sl1.z + xr1.z); v = fmaxf(v, 0.2f * v); part = fmaf(v, at1.z, part);
        v = fmaf(a, w1.w, sl1.w + xr1.w); v = fmaxf(v, 0.2f * v); part = fmaf(v, at1.w, part);
        part += __shfl_xor_sync(0xffffffffu, part, 1);
        part += __shfl_xor_sync(0xffffffffu, part, 2);
        part += __shfl_xor_sync(0xffffffffu, part, 4);
        float pe = __expf(part);   // identical in every group
        acc0.x = fmaf(pe, sl0.x, acc0.x);
        acc0.y = fmaf(pe, sl0.y, acc0.y);
        acc0.z = fmaf(pe, sl0.z, acc0.z);
        acc0.w = fmaf(pe, sl0.w, acc0.w);
        acc1.x = fmaf(pe, sl1.x, acc1.x);
        acc1.y = fmaf(pe, sl1.y, acc1.y);
        acc1.z = fmaf(pe, sl1.z, acc1.z);
        acc1.w = fmaf(pe, sl1.w, acc1.w);
        den += pe;
        if (lane == 0) g_csr[beg] = make_int2(node, __float_as_int(a));
    }

    float inv = 1.f / (den + 1e-16f);
    float4 b0 = ((const float4*)bias)[2 * gl];
    float4 b1 = ((const float4*)bias)[2 * gl + 1];
    float4 o0, o1;
    o0.x = acc0.x * inv + b0.x; o0.x = o0.x > 0.f ? o0.x : (__expf(o0.x) - 1.f);
    o0.y = acc0.y * inv + b0.y; o0.y = o0.y > 0.f ? o0.y : (__expf(o0.y) - 1.f);
    o0.z = acc0.z * inv + b0.z; o0.z = o0.z > 0.f ? o0.z : (__expf(o0.z) - 1.f);
    o0.w = acc0.w * inv + b0.w; o0.w = o0.w > 0.f ? o0.w : (__expf(o0.w) - 1.f);
    o1.x = acc1.x * inv + b1.x; o1.x = o1.x > 0.f ? o1.x : (__expf(o1.x) - 1.f);
    o1.y = acc1.y * inv + b1.y; o1.y = o1.y > 0.f ? o1.y : (__expf(o1.y) - 1.f);
    o1.z = acc1.z * inv + b1.z; o1.z = o1.z > 0.f ? o1.z : (__expf(o1.z) - 1.f);
    o1.w = acc1.w * inv + b1.w; o1.w = o1.w > 0.f ? o1.w : (__expf(o1.w) - 1.f);

    if (grp == 0) {   // lanes 0..7 hold the full 64 channels
        ((float4*)g_h)[node * 16 + 2 * gl] = o0;
        ((float4*)g_h)[node * 16 + 2 * gl + 1] = o1;
        if (!FIRST) {
            int g = batch[node];
            float* pb = &g_pool[g * 64 + 8 * gl];
            atomicAdd(pb + 0, o0.x); atomicAdd(pb + 1, o0.y);
            atomicAdd(pb + 2, o0.z); atomicAdd(pb + 3, o0.w);
            atomicAdd(pb + 4, o1.x); atomicAdd(pb + 5, o1.y);
            atomicAdd(pb + 6, o1.z); atomicAdd(pb + 7, o1.w);
            if (lane == 0) atomicAdd(&g_pcnt[g], 1.f);
        }
    }
}

// ---------------- head: mean-pool divide -> fc1 -> relu -> bn -> fc3 ----------------
__global__ void head_kernel(const float* __restrict__ Wfc1, const float* __restrict__ bfc1,
                            const float* __restrict__ gam, const float* __restrict__ bet,
                            const float* __restrict__ mean, const float* __restrict__ var,
                            const float* __restrict__ Wfc3, const float* __restrict__ bfc3,
                            float* __restrict__ out) {
    int g = threadIdx.x;
    if (g >= GG) return;
    float inv_cnt = 1.0f / fmaxf(g_pcnt[g], 1.0f);
    float pooled[64];
#pragma unroll
    for (int c = 0; c < 64; c++) pooled[c] = g_pool[g * 64 + c] * inv_cnt;
    float acc = bfc3[0];
    for (int j = 0; j < 32; j++) {
        float z = bfc1[j];
#pragma unroll
        for (int c = 0; c < 64; c++) z = fmaf(pooled[c], Wfc1[c * 32 + j], z);
        z = fmaxf(z, 0.f);
        z = (z - mean[j]) * rsqrtf(var[j] + 1e-5f) * gam[j] + bet[j];
        acc = fmaf(z, Wfc3[j], acc);
    }
    out[g] = acc;
}

// ---------------- launch ----------------
extern "C" void kernel_launch(void* const* d_in, const int* in_sizes, int n_in,
                              void* d_out, int out_size) {
    const float* x = (const float*)d_in[0];
    const int* ei = (const int*)d_in[1];
    const float* ea = (const float*)d_in[2];
    const int* batch = (const int*)d_in[3];
    const float* Wl1 = (const float*)d_in[4];
    const float* bl1 = (const float*)d_in[5];
    const float* Wr1 = (const float*)d_in[6];
    const float* br1 = (const float*)d_in[7];
    const float* We1 = (const float*)d_in[8];
    const float* att1 = (const float*)d_in[9];
    const float* bias1 = (const float*)d_in[10];
    const float* Wl2 = (const float*)d_in[11];
    const float* bl2 = (const float*)d_in[12];
    const float* Wr2 = (const float*)d_in[13];
    const float* br2 = (const float*)d_in[14];
    const float* We2 = (const float*)d_in[15];
    const float* att2 = (const float*)d_in[16];
    const float* bias2 = (const float*)d_in[17];
    const float* Wfc1 = (const float*)d_in[18];
    const float* bfc1 = (const float*)d_in[19];
    const float* bng = (const float*)d_in[20];
    const float* bnb = (const float*)d_in[21];
    const float* bnm = (const float*)d_in[22];
    const float* bnv = (const float*)d_in[23];
    const float* Wfc3 = (const float*)d_in[24];
    const float* bfc3 = (const float*)d_in[25];
    float* out = (float*)d_out;

    const int node_warp_grid = (NN * 32 + 255) / 256;

    // ---- CSR build (dst-sorted, atomic-free scatter) ----
    init_kernel<<<(NN + 255) / 256, 256>>>();
    count_kernel<<<(EE + 255) / 256, 256>>>(ei);
    scan1_kernel<<<NBLK, SCAN_BLK>>>();
    scan2_kernel<<<1, 64>>>();
    scan3_kernel<<<NBLK, SCAN_BLK>>>();
    scatter_kernel<<<(EE + 255) / 256, 256>>>(ei, ea);

    // ---- GATv2 layer 1 (fused self-loop mean) ----
    linear_kernel<128, false><<<NN / 16, dim3(16, 16)>>>(x, Wl1, bl1, Wr1, br1);
    gat_node_kernel<true><<<node_warp_grid, 256>>>(We1, att1, bias1, batch);

    // ---- GATv2 layer 2 (pools) ----
    linear_kernel<64, true><<<NN / 16, dim3(16, 16)>>>(nullptr, Wl2, bl2, Wr2, br2);
    gat_node_kernel<false><<<node_warp_grid, 256>>>(We2, att2, bias2, batch);

    // ---- head ----
    head_kernel<<<1, 64>>>(Wfc1, bfc1, bng, bnb, bnm, bnv, Wfc3, bfc3, out);
}

// round 11
// speedup vs baseline: 1.6745x; 1.6745x over previous
#include <cuda_runtime.h>
#include <math_constants.h>

#define NN 50000
#define EE 1600000
#define EP (EE + NN)
#define GG 64
#define IND 128
#define HIDD 64
#define SCAN_BLK 1024
#define NBLK ((NN + SCAN_BLK - 1) / SCAN_BLK)

// ---------------- device scratch (no allocations allowed) ----------------
__device__ __align__(16) float g_xl[NN * HIDD];
__device__ __align__(16) float g_xr[NN * HIDD];
__device__ __align__(16) float g_h[NN * HIDD];
__device__ int g_deg[NN];          // in-degree incl. self loop
__device__ int g_off[NN + 1];      // CSR offsets (exclusive)
__device__ int g_rank[EE];         // per-edge slot within its dst segment
__device__ __align__(8) int2 g_csr[EP];  // packed {src, attr_bits}
__device__ int g_bsum[NBLK + 1];   // scan block sums
__device__ float g_pool[GG * HIDD];
__device__ float g_pcnt[GG];

// ---------------- init ----------------
__global__ void init_kernel() {
    int i = blockIdx.x * blockDim.x + threadIdx.x;
    if (i < NN) g_deg[i] = 1;   // slot 0 = self loop
    if (i < GG * HIDD) g_pool[i] = 0.f;
    if (i < GG) g_pcnt[i] = 0.f;
}

// ---------------- CSR build ----------------
// count + record rank: atomic return value is this edge's slot within its dst segment
__global__ void count_kernel(const int* __restrict__ ei) {
    int e = blockIdx.x * blockDim.x + threadIdx.x;
    if (e >= EE) return;
    g_rank[e] = atomicAdd(&g_deg[ei[EE + e]], 1);   // in [1, indeg]; slot 0 = self loop
}

// per-block inclusive scan (Hillis-Steele) of degrees
__global__ void scan1_kernel() {
    __shared__ int s[SCAN_BLK];
    int t = threadIdx.x;
    int i = blockIdx.x * SCAN_BLK + t;
    int v = (i < NN) ? g_deg[i] : 0;
    s[t] = v;
    __syncthreads();
#pragma unroll
    for (int o = 1; o < SCAN_BLK; o <<= 1) {
        int x = (t >= o) ? s[t - o] : 0;
        __syncthreads();
        s[t] += x;
        __syncthreads();
    }
    if (i < NN) g_off[i] = s[t];
    if (t == SCAN_BLK - 1) g_bsum[blockIdx.x] = s[t];
}

// exclusive scan of NBLK block sums (parallel, one 64-thread block)
__global__ void scan2_kernel() {
    __shared__ int s[64];
    int t = threadIdx.x;
    int v = (t < NBLK) ? g_bsum[t] : 0;
    s[t] = v;
    __syncthreads();
#pragma unroll
    for (int o = 1; o < 64; o <<= 1) {
        int x = (t >= o) ? s[t - o] : 0;
        __syncthreads();
        s[t] += x;
        __syncthreads();
    }
    if (t < NBLK) g_bsum[t] = s[t] - v;  // exclusive
}

__global__ void scan3_kernel() {
    int i = blockIdx.x * SCAN_BLK + threadIdx.x;
    if (i < NN) g_off[i] = g_off[i] - g_deg[i] + g_bsum[blockIdx.x];
    if (i == 0) g_off[NN] = EP;
}

// atomic-free scatter: slot fully determined by off + rank; one packed 8B store
__global__ void scatter_kernel(const int* __restrict__ ei, const float* __restrict__ ea) {
    int e = blockIdx.x * blockDim.x + threadIdx.x;
    if (e >= EE) return;
    int d = ei[EE + e];
    g_csr[g_off[d] + g_rank[e]] = make_int2(ei[e], __float_as_int(ea[e]));
}

// self-loop attr = mean of real incoming edge attrs; warp per node
__global__ void selfloop_kernel() {
    int gtid = blockIdx.x * blockDim.x + threadIdx.x;
    int node = gtid >> 5, lane = gtid & 31;
    if (node >= NN) return;
    int beg = g_off[node], end = g_off[node + 1];
    float s = 0.f;
    for (int p = beg + 1 + lane; p < end; p += 32) s += __int_as_float(g_csr[p].y);
#pragma unroll
    for (int o = 16; o; o >>= 1) s += __shfl_xor_sync(0xffffffffu, s, o);
    if (lane == 0) {
        int cnt = end - beg - 1;
        g_csr[beg] = make_int2(node, __float_as_int(s / fmaxf((float)cnt, 1.f)));
    }
}

// ---------------- node linear transforms: xl = h@Wl+bl, xr = h@Wr+br ----------------
// blockDim = (64, 4): 4 nodes per block, thread.x = out channel
template <int K, bool FROM_H>
__global__ void linear_kernel(const float* __restrict__ x,
                              const float* __restrict__ Wl, const float* __restrict__ bl,
                              const float* __restrict__ Wr, const float* __restrict__ br) {
    __shared__ float sx[4][K];
    int node = blockIdx.x * 4 + threadIdx.y;
    int c = threadIdx.x;
    if (node < NN) {
        const float* src = FROM_H ? (g_h + node * K) : (x + node * K);
        for (int k = c; k < K; k += 64) sx[threadIdx.y][k] = src[k];
    }
    __syncthreads();
    if (node >= NN) return;
    float al = bl[c], ar = br[c];
#pragma unroll 8
    for (int k = 0; k < K; k++) {
        float xv = sx[threadIdx.y][k];
        al = fmaf(xv, Wl[k * 64 + c], al);
        ar = fmaf(xv, Wr[k * 64 + c], ar);
    }
    g_xl[node * 64 + c] = al;
    g_xr[node * 64 + c] = ar;
}

// ---------------- fused GAT aggregation: warp per node, plain softmax ----------------
// Softmax is shift-invariant; logits here are O(1) so no max subtraction is
// needed. Single pass: one LDG.64 broadcast (packed src+attr) + one float2
// gather per edge, warp butterfly for the logit, exp-weighted accumulate.
__global__ void gat_node_kernel(const float* __restrict__ We, const float* __restrict__ att,
                                const float* __restrict__ bias, const int* __restrict__ batch,
                                int do_pool) {
    int gtid = blockIdx.x * blockDim.x + threadIdx.x;
    int node = gtid >> 5, lane = gtid & 31;
    if (node >= NN) return;
    int beg = g_off[node], end = g_off[node + 1];

    float2 xr2 = ((const float2*)g_xr)[node * 32 + lane];
    float2 w = ((const float2*)We)[lane];
    float2 at = ((const float2*)att)[lane];

    float den = 0.f;
    float accx = 0.f, accy = 0.f;

#pragma unroll 2
    for (int p = beg; p < end; p++) {
        int2 c2 = __ldg(&g_csr[p]);        // broadcast: {src, attr}
        int s = c2.x;
        float a = __int_as_float(c2.y);
        float2 xl = ((const float2*)g_xl)[s * 32 + lane];
        float v0 = xl.x + xr2.x + a * w.x;
        v0 = v0 > 0.f ? v0 : 0.2f * v0;
        float v1 = xl.y + xr2.y + a * w.y;
        v1 = v1 > 0.f ? v1 : 0.2f * v1;
        float sum = v0 * at.x + v1 * at.y;
#pragma unroll
        for (int o = 16; o; o >>= 1) sum += __shfl_xor_sync(0xffffffffu, sum, o);
        float pe = __expf(sum);            // logits are O(1): no overflow risk
        accx = fmaf(pe, xl.x, accx);
        accy = fmaf(pe, xl.y, accy);
        den += pe;
    }

    float inv = 1.f / (den + 1e-16f);
    float v0 = accx * inv + bias[2 * lane];
    v0 = v0 > 0.f ? v0 : (__expf(v0) - 1.f);   // ELU
    float v1 = accy * inv + bias[2 * lane + 1];
    v1 = v1 > 0.f ? v1 : (__expf(v1) - 1.f);
    ((float2*)g_h)[node * 32 + lane] = make_float2(v0, v1);

    if (do_pool) {
        int g = batch[node];
        atomicAdd(&g_pool[g * 64 + 2 * lane], v0);
        atomicAdd(&g_pool[g * 64 + 2 * lane + 1], v1);
        if (lane == 0) atomicAdd(&g_pcnt[g], 1.f);
    }
}

// ---------------- head: mean-pool divide -> fc1 -> relu -> bn -> fc3 ----------------
__global__ void head_kernel(const float* __restrict__ Wfc1, const float* __restrict__ bfc1,
                            const float* __restrict__ gam, const float* __restrict__ bet,
                            const float* __restrict__ mean, const float* __restrict__ var,
                            const float* __restrict__ Wfc3, const float* __restrict__ bfc3,
                            float* __restrict__ out) {
    int g = threadIdx.x;
    if (g >= GG) return;
    float inv_cnt = 1.0f / fmaxf(g_pcnt[g], 1.0f);
    float pooled[64];
#pragma unroll
    for (int c = 0; c < 64; c++) pooled[c] = g_pool[g * 64 + c] * inv_cnt;
    float acc = bfc3[0];
    for (int j = 0; j < 32; j++) {
        float z = bfc1[j];
#pragma unroll
        for (int c = 0; c < 64; c++) z = fmaf(pooled[c], Wfc1[c * 32 + j], z);
        z = fmaxf(z, 0.f);
        z = (z - mean[j]) * rsqrtf(var[j] + 1e-5f) * gam[j] + bet[j];
        acc = fmaf(z, Wfc3[j], acc);
    }
    out[g] = acc;
}

// ---------------- launch ----------------
extern "C" void kernel_launch(void* const* d_in, const int* in_sizes, int n_in,
                              void* d_out, int out_size) {
    const float* x = (const float*)d_in[0];
    const int* ei = (const int*)d_in[1];
    const float* ea = (const float*)d_in[2];
    const int* batch = (const int*)d_in[3];
    const float* Wl1 = (const float*)d_in[4];
    const float* bl1 = (const float*)d_in[5];
    const float* Wr1 = (const float*)d_in[6];
    const float* br1 = (const float*)d_in[7];
    const float* We1 = (const float*)d_in[8];
    const float* att1 = (const float*)d_in[9];
    const float* bias1 = (const float*)d_in[10];
    const float* Wl2 = (const float*)d_in[11];
    const float* bl2 = (const float*)d_in[12];
    const float* Wr2 = (const float*)d_in[13];
    const float* br2 = (const float*)d_in[14];
    const float* We2 = (const float*)d_in[15];
    const float* att2 = (const float*)d_in[16];
    const float* bias2 = (const float*)d_in[17];
    const float* Wfc1 = (const float*)d_in[18];
    const float* bfc1 = (const float*)d_in[19];
    const float* bng = (const float*)d_in[20];
    const float* bnb = (const float*)d_in[21];
    const float* bnm = (const float*)d_in[22];
    const float* bnv = (const float*)d_in[23];
    const float* Wfc3 = (const float*)d_in[24];
    const float* bfc3 = (const float*)d_in[25];
    float* out = (float*)d_out;

    const int node_warp_grid = (NN * 32 + 255) / 256;

    // ---- CSR build (dst-sorted, atomic-free scatter) ----
    init_kernel<<<(NN + 255) / 256, 256>>>();
    count_kernel<<<(EE + 255) / 256, 256>>>(ei);
    scan1_kernel<<<NBLK, SCAN_BLK>>>();
    scan2_kernel<<<1, 64>>>();
    scan3_kernel<<<NBLK, SCAN_BLK>>>();
    scatter_kernel<<<(EE + 255) / 256, 256>>>(ei, ea);
    selfloop_kernel<<<node_warp_grid, 256>>>();

    // ---- GATv2 layer 1 ----
    linear_kernel<128, false><<<(NN + 3) / 4, dim3(64, 4)>>>(x, Wl1, bl1, Wr1, br1);
    gat_node_kernel<<<node_warp_grid, 256>>>(We1, att1, bias1, batch, 0);

    // ---- GATv2 layer 2 ----
    linear_kernel<64, true><<<(NN + 3) / 4, dim3(64, 4)>>>(nullptr, Wl2, bl2, Wr2, br2);
    gat_node_kernel<<<node_warp_grid, 256>>>(We2, att2, bias2, batch, 1);

    // ---- head ----
    head_kernel<<<1, 64>>>(Wfc1, bfc1, bng, bnb, bnm, bnv, Wfc3, bfc3, out);
}